// round 15
// baseline (speedup 1.0000x reference)
#include <cuda_runtime.h>
#include <cuda_bf16.h>
#include <cstdint>

// Problem constants
static constexpr int S = 4096;
static constexpr int D = 1024;
static constexpr int H = 2816;
static constexpr int E = 16;
static constexpr int TOPK = 2;
static constexpr int P = S * TOPK;   // 8192 dispatched rows

// GEMM tiling (proven shape; single-barrier 3-stage ring)
static constexpr int BM = 128;
static constexpr int BN = 64;
static constexpr int BK = 32;
static constexpr int NSTAGE = 3;
static constexpr int LDA = 40;   // smem row pitch in bf16 (conflict-free for ldmatrix)
static constexpr int LDB = 40;

// -------- device scratch (allocation-free: static device globals) --------
__device__ __nv_bfloat16 g_xb[(size_t)S * D];       // x in bf16, token order    (8 MB)
__device__ __nv_bfloat16 g_h[(size_t)P * H];        // silu(g)*u, bf16           (45 MB)
__device__ __nv_bfloat16 g_y[(size_t)P * D];        // down-proj result, bf16    (16 MB)
__device__ __nv_bfloat16 g_wg[(size_t)E * H * D];   // w_gate bf16               (92 MB)
__device__ __nv_bfloat16 g_wu[(size_t)E * H * D];   // w_up bf16                 (92 MB)
__device__ __nv_bfloat16 g_wd[(size_t)E * D * H];   // w_down bf16               (92 MB)
__device__ float         g_rw[P];                   // normalized router weights
__device__ int           g_expert[P];               // expert id per (token,k)
__device__ int           g_row_of_pair[P];          // pair -> sorted row
__device__ int           g_perm[P];                 // sorted row -> pair
__device__ int           g_cnt[E];
__device__ int           g_off[E];

// ---------------- small helpers ----------------
__device__ __forceinline__ void ldsm_x4(uint32_t& r0, uint32_t& r1, uint32_t& r2, uint32_t& r3,
                                        const __nv_bfloat16* p) {
    uint32_t addr = (uint32_t)__cvta_generic_to_shared(p);
    asm volatile("ldmatrix.sync.aligned.m8n8.x4.shared.b16 {%0,%1,%2,%3}, [%4];\n"
                 : "=r"(r0), "=r"(r1), "=r"(r2), "=r"(r3) : "r"(addr));
}

__device__ __forceinline__ void mma16816(float* c, const uint32_t* a, const uint32_t* b) {
    asm volatile("mma.sync.aligned.m16n8k16.row.col.f32.bf16.bf16.f32 "
                 "{%0,%1,%2,%3}, {%4,%5,%6,%7}, {%8,%9}, {%0,%1,%2,%3};\n"
                 : "+f"(c[0]), "+f"(c[1]), "+f"(c[2]), "+f"(c[3])
                 : "r"(a[0]), "r"(a[1]), "r"(a[2]), "r"(a[3]), "r"(b[0]), "r"(b[1]));
}

__device__ __forceinline__ void cp_async16(const __nv_bfloat16* smem_dst, const __nv_bfloat16* gsrc,
                                           bool valid) {
    uint32_t d = (uint32_t)__cvta_generic_to_shared(smem_dst);
    int sz = valid ? 16 : 0;
    asm volatile("cp.async.cg.shared.global [%0], [%1], 16, %2;\n" :: "r"(d), "l"(gsrc), "r"(sz));
}
__device__ __forceinline__ void cp_commit() { asm volatile("cp.async.commit_group;\n" ::: "memory"); }
template <int N>
__device__ __forceinline__ void cp_wait() { asm volatile("cp.async.wait_group %0;\n" :: "n"(N) : "memory"); }

// bf16 round-trip: emulate the reference's ragged_dot bf16 output then fp32 cast
__device__ __forceinline__ float bf16_round(float v) {
    return __bfloat162float(__float2bfloat16_rn(v));
}
// fast silu: __expf error (~1e-6 rel) is absorbed by the subsequent bf16 rounding
__device__ __forceinline__ float fast_silu_mul(float g, float u) {
    return __fdividef(g, 1.f + __expf(-g)) * u;
}

// ---------------- kernel 1: fp32->bf16 conversion (weights + x) + counter init ----------------
__global__ void cvt_all_kernel(const float4* __restrict__ Wg, const float4* __restrict__ Wu,
                               const float4* __restrict__ Wd, const float4* __restrict__ X,
                               __nv_bfloat162* __restrict__ og, __nv_bfloat162* __restrict__ ou,
                               __nv_bfloat162* __restrict__ od, __nv_bfloat162* __restrict__ ox,
                               int n4, int xn4) {
    int i = blockIdx.x * blockDim.x + threadIdx.x;
    if (blockIdx.x == 0 && threadIdx.x < E) g_cnt[threadIdx.x] = 0;
    if (i >= 3 * n4 + xn4) return;
    const float4* src;
    __nv_bfloat162* dst;
    int j = i;
    if (j < n4)            { src = Wg; dst = og; }
    else if (j < 2 * n4)   { src = Wu; dst = ou; j -= n4; }
    else if (j < 3 * n4)   { src = Wd; dst = od; j -= 2 * n4; }
    else                   { src = X;  dst = ox; j -= 3 * n4; }
    float4 v = src[j];
    dst[j * 2 + 0] = __floats2bfloat162_rn(v.x, v.y);
    dst[j * 2 + 1] = __floats2bfloat162_rn(v.z, v.w);
}

// ---------------- kernel 2: router (one warp per token) ----------------
__global__ void router_kernel(const float* __restrict__ x, const float* __restrict__ gw,
                              float* __restrict__ logits_out, float* __restrict__ topi_out) {
    int gwarp = (blockIdx.x * blockDim.x + threadIdx.x) >> 5;
    int lane = threadIdx.x & 31;
    if (gwarp >= S) return;

    const float4* xr = (const float4*)(x + (size_t)gwarp * D);
    float acc[E];
#pragma unroll
    for (int e = 0; e < E; e++) acc[e] = 0.f;
    for (int j = lane; j < D / 4; j += 32) {
        float4 xv = xr[j];
#pragma unroll
        for (int e = 0; e < E; e++) {
            float4 wv = ((const float4*)(gw + (size_t)e * D))[j];
            acc[e] += xv.x * wv.x + xv.y * wv.y + xv.z * wv.z + xv.w * wv.w;
        }
    }
#pragma unroll
    for (int e = 0; e < E; e++) {
#pragma unroll
        for (int o = 16; o > 0; o >>= 1) acc[e] += __shfl_xor_sync(0xffffffffu, acc[e], o);
    }
    if (logits_out && lane < E) logits_out[(size_t)gwarp * E + lane] = acc[lane];

    if (lane == 0) {
        float m = acc[0];
#pragma unroll
        for (int e = 1; e < E; e++) m = fmaxf(m, acc[e]);
        float p[E];
        float sum = 0.f;
#pragma unroll
        for (int e = 0; e < E; e++) { p[e] = expf(acc[e] - m); sum += p[e]; }
        // top-2 with lowest-index tie break (matches jax.lax.top_k)
        int i0 = 0;
#pragma unroll
        for (int e = 1; e < E; e++) if (p[e] > p[i0]) i0 = e;
        int i1 = (i0 == 0) ? 1 : 0;
#pragma unroll
        for (int e = 0; e < E; e++) { if (e == i0) continue; if (p[e] > p[i1]) i1 = e; }
        float w0 = p[i0] / sum, w1 = p[i1] / sum;
        float inv = 1.f / (w0 + w1);
        g_expert[gwarp * 2 + 0] = i0;
        g_expert[gwarp * 2 + 1] = i1;
        g_rw[gwarp * 2 + 0] = w0 * inv;
        g_rw[gwarp * 2 + 1] = w1 * inv;
        atomicAdd(&g_cnt[i0], 1);
        atomicAdd(&g_cnt[i1], 1);
        if (topi_out) {
            topi_out[gwarp * 2 + 0] = (float)i0;
            topi_out[gwarp * 2 + 1] = (float)i1;
        }
    }
}

// ---------------- kernel 3: fused scan + scatter (single block) ----------------
// Within-expert order need not be stable: row_of_pair tracks the exact placement
// and grouped-GEMM output rows are recovered through it.
__global__ void scan_scatter_kernel() {
    __shared__ int scur[E];
    int t = threadIdx.x;
    if (t == 0) {
        int o = 0;
        for (int e = 0; e < E; e++) { g_off[e] = o; scur[e] = o; o += g_cnt[e]; }
    }
    __syncthreads();
    for (int p = t; p < P; p += blockDim.x) {
        int e = g_expert[p];
        int pos = atomicAdd(&scur[e], 1);
        g_row_of_pair[p] = pos;
        g_perm[pos] = p;
    }
}

// ---------------- kernel 4: fused gate/up grouped GEMM + SwiGLU ----------------
// grid: (H/BN, 64, E), 256 threads (8 warps, 4x2). A rows resolved through g_perm
// into g_xb (token order) — no gather kernel, no duplicated activation buffer.
// 3-stage cp.async ring, ONE __syncthreads per K-step.
__global__ __launch_bounds__(256, 2) void gemm1_kernel() {
    int e = blockIdx.z;
    int cnt = g_cnt[e];
    int mt = blockIdx.y;
    if (mt * BM >= cnt) return;
    int nt = blockIdx.x;
    int row0 = g_off[e] + mt * BM;
    int row_end = g_off[e] + cnt;

    __shared__ __nv_bfloat16 As[NSTAGE][BM * LDA];
    __shared__ __nv_bfloat16 Bgs[NSTAGE][BN * LDB];
    __shared__ __nv_bfloat16 Bus[NSTAGE][BN * LDB];

    int tid = threadIdx.x, lane = tid & 31, warp = tid >> 5;
    int wm = warp >> 1, wn = warp & 1;

    float accg[2][4][4];
    float accu[2][4][4];
#pragma unroll
    for (int a = 0; a < 2; a++)
#pragma unroll
        for (int b = 0; b < 4; b++)
#pragma unroll
            for (int c = 0; c < 4; c++) { accg[a][b][c] = 0.f; accu[a][b][c] = 0.f; }

    const __nv_bfloat16* wg_base = g_wg + ((size_t)e * H + (size_t)nt * BN) * D;
    const __nv_bfloat16* wu_base = g_wu + ((size_t)e * H + (size_t)nt * BN) * D;

    int ar0 = tid >> 2, aseg0 = tid & 3;             // A chunk 0
    int ar1 = (tid + 256) >> 2, aseg1 = tid & 3;     // A chunk 1
    int br = tid >> 2, bseg = tid & 3;               // B chunk

    // Resolve this thread's two A rows through the permutation once.
    bool v0 = row0 + ar0 < row_end;
    bool v1 = row0 + ar1 < row_end;
    int tok0 = v0 ? (g_perm[row0 + ar0] >> 1) : 0;
    int tok1 = v1 ? (g_perm[row0 + ar1] >> 1) : 0;
    const __nv_bfloat16* a0p = g_xb + (size_t)tok0 * D + aseg0 * 8;
    const __nv_bfloat16* a1p = g_xb + (size_t)tok1 * D + aseg1 * 8;

    auto load_stage = [&](int st, int k0) {
        cp_async16(&As[st][ar0 * LDA + aseg0 * 8], a0p + k0, v0);
        cp_async16(&As[st][ar1 * LDA + aseg1 * 8], a1p + k0, v1);
        cp_async16(&Bgs[st][br * LDB + bseg * 8], wg_base + (size_t)br * D + k0 + bseg * 8, true);
        cp_async16(&Bus[st][br * LDB + bseg * 8], wu_base + (size_t)br * D + k0 + bseg * 8, true);
    };

    constexpr int NK = D / BK;  // 32
    load_stage(0, 0);
    cp_commit();
    load_stage(1, BK);
    cp_commit();

    for (int ks = 0; ks < NK; ks++) {
        int cur = ks % NSTAGE;
        if (ks + 1 < NK) cp_wait<1>(); else cp_wait<0>();
        __syncthreads();
        if (ks + 2 < NK) {
            load_stage((ks + 2) % NSTAGE, (ks + 2) * BK);
            cp_commit();
        }

#pragma unroll
        for (int kk = 0; kk < BK; kk += 16) {
            uint32_t af[2][4];
#pragma unroll
            for (int mf = 0; mf < 2; mf++) {
                int mbase = wm * 32 + mf * 16;
                int row = mbase + (lane & 7) + ((lane >> 3) & 1) * 8;
                int col = kk + (lane >> 4) * 8;
                ldsm_x4(af[mf][0], af[mf][1], af[mf][2], af[mf][3], &As[cur][row * LDA + col]);
            }
            uint32_t bg[4][2], bu[4][2];
#pragma unroll
            for (int nfp = 0; nfp < 2; nfp++) {
                int tile = lane >> 3;
                int n = wn * 32 + nfp * 16 + (tile >> 1) * 8 + (lane & 7);
                int c = kk + (tile & 1) * 8;
                ldsm_x4(bg[nfp * 2][0], bg[nfp * 2][1], bg[nfp * 2 + 1][0], bg[nfp * 2 + 1][1],
                        &Bgs[cur][n * LDB + c]);
                ldsm_x4(bu[nfp * 2][0], bu[nfp * 2][1], bu[nfp * 2 + 1][0], bu[nfp * 2 + 1][1],
                        &Bus[cur][n * LDB + c]);
            }
#pragma unroll
            for (int mf = 0; mf < 2; mf++)
#pragma unroll
                for (int nf = 0; nf < 4; nf++) {
                    mma16816(&accg[mf][nf][0], af[mf], bg[nf]);
                    mma16816(&accu[mf][nf][0], af[mf], bu[nf]);
                }
        }
    }

    // Epilogue: reference rounds g and u to bf16 (ragged_dot output dtype),
    // casts to fp32, applies silu in fp32, multiplies, then casts to bf16.
    int gr = lane >> 2, gc = (lane & 3) * 2;
#pragma unroll
    for (int mf = 0; mf < 2; mf++) {
#pragma unroll
        for (int nf = 0; nf < 4; nf++) {
            int col = nt * BN + wn * 32 + nf * 8 + gc;
            int r0g = row0 + wm * 32 + mf * 16 + gr;
            int r1g = r0g + 8;
            if (r0g < row_end) {
                float gg0 = bf16_round(accg[mf][nf][0]);
                float gg1 = bf16_round(accg[mf][nf][1]);
                float uu0 = bf16_round(accu[mf][nf][0]);
                float uu1 = bf16_round(accu[mf][nf][1]);
                float s0 = fast_silu_mul(gg0, uu0);
                float s1 = fast_silu_mul(gg1, uu1);
                *(__nv_bfloat162*)(g_h + (size_t)r0g * H + col) = __floats2bfloat162_rn(s0, s1);
            }
            if (r1g < row_end) {
                float gg2 = bf16_round(accg[mf][nf][2]);
                float gg3 = bf16_round(accg[mf][nf][3]);
                float uu2 = bf16_round(accu[mf][nf][2]);
                float uu3 = bf16_round(accu[mf][nf][3]);
                float s2 = fast_silu_mul(gg2, uu2);
                float s3 = fast_silu_mul(gg3, uu3);
                *(__nv_bfloat162*)(g_h + (size_t)r1g * H + col) = __floats2bfloat162_rn(s2, s3);
            }
        }
    }
}

// ---------------- kernel 5: down-proj grouped GEMM ----------------
// grid: (D/BN, 64, E), 256 threads. Same single-barrier 3-stage ring.
__global__ __launch_bounds__(256, 2) void gemm2_kernel() {
    int e = blockIdx.z;
    int cnt = g_cnt[e];
    int mt = blockIdx.y;
    if (mt * BM >= cnt) return;
    int nt = blockIdx.x;
    int row0 = g_off[e] + mt * BM;
    int row_end = g_off[e] + cnt;

    __shared__ __nv_bfloat16 As[NSTAGE][BM * LDA];
    __shared__ __nv_bfloat16 Bs[NSTAGE][BN * LDB];

    int tid = threadIdx.x, lane = tid & 31, warp = tid >> 5;
    int wm = warp >> 1, wn = warp & 1;

    float acc[2][4][4];
#pragma unroll
    for (int a = 0; a < 2; a++)
#pragma unroll
        for (int b = 0; b < 4; b++)
#pragma unroll
            for (int c = 0; c < 4; c++) acc[a][b][c] = 0.f;

    const __nv_bfloat16* wd_base = g_wd + ((size_t)e * D + (size_t)nt * BN) * H;

    int ar0 = tid >> 2, aseg0 = tid & 3;
    int ar1 = (tid + 256) >> 2, aseg1 = tid & 3;
    int br = tid >> 2, bseg = tid & 3;

    auto load_stage = [&](int st, int k0) {
        cp_async16(&As[st][ar0 * LDA + aseg0 * 8],
                   g_h + (size_t)(row0 + ar0) * H + k0 + aseg0 * 8, row0 + ar0 < row_end);
        cp_async16(&As[st][ar1 * LDA + aseg1 * 8],
                   g_h + (size_t)(row0 + ar1) * H + k0 + aseg1 * 8, row0 + ar1 < row_end);
        cp_async16(&Bs[st][br * LDB + bseg * 8], wd_base + (size_t)br * H + k0 + bseg * 8, true);
    };

    constexpr int NK = H / BK;  // 88
    load_stage(0, 0);
    cp_commit();
    load_stage(1, BK);
    cp_commit();

    for (int ks = 0; ks < NK; ks++) {
        int cur = ks % NSTAGE;
        if (ks + 1 < NK) cp_wait<1>(); else cp_wait<0>();
        __syncthreads();
        if (ks + 2 < NK) {
            load_stage((ks + 2) % NSTAGE, (ks + 2) * BK);
            cp_commit();
        }

#pragma unroll
        for (int kk = 0; kk < BK; kk += 16) {
            uint32_t af[2][4];
#pragma unroll
            for (int mf = 0; mf < 2; mf++) {
                int mbase = wm * 32 + mf * 16;
                int row = mbase + (lane & 7) + ((lane >> 3) & 1) * 8;
                int col = kk + (lane >> 4) * 8;
                ldsm_x4(af[mf][0], af[mf][1], af[mf][2], af[mf][3], &As[cur][row * LDA + col]);
            }
            uint32_t bf[4][2];
#pragma unroll
            for (int nfp = 0; nfp < 2; nfp++) {
                int tile = lane >> 3;
                int n = wn * 32 + nfp * 16 + (tile >> 1) * 8 + (lane & 7);
                int c = kk + (tile & 1) * 8;
                ldsm_x4(bf[nfp * 2][0], bf[nfp * 2][1], bf[nfp * 2 + 1][0], bf[nfp * 2 + 1][1],
                        &Bs[cur][n * LDB + c]);
            }
#pragma unroll
            for (int mf = 0; mf < 2; mf++)
#pragma unroll
                for (int nf = 0; nf < 4; nf++) mma16816(&acc[mf][nf][0], af[mf], bf[nf]);
        }
    }

    int gr = lane >> 2, gc = (lane & 3) * 2;
#pragma unroll
    for (int mf = 0; mf < 2; mf++) {
#pragma unroll
        for (int nf = 0; nf < 4; nf++) {
            int col = nt * BN + wn * 32 + nf * 8 + gc;
            int r0g = row0 + wm * 32 + mf * 16 + gr;
            int r1g = r0g + 8;
            if (r0g < row_end)
                *(__nv_bfloat162*)(g_y + (size_t)r0g * D + col) =
                    __floats2bfloat162_rn(acc[mf][nf][0], acc[mf][nf][1]);
            if (r1g < row_end)
                *(__nv_bfloat162*)(g_y + (size_t)r1g * D + col) =
                    __floats2bfloat162_rn(acc[mf][nf][2], acc[mf][nf][3]);
        }
    }
}

// ---------------- kernel 6: weighted combine (fp32 math over bf16 y) ----------------
__global__ void combine_kernel(float* __restrict__ out) {
    int idx = blockIdx.x * blockDim.x + threadIdx.x;
    if (idx >= S * (D / 4)) return;
    int s = idx / (D / 4);
    int j = idx % (D / 4);
    int r0 = g_row_of_pair[2 * s + 0];
    int r1 = g_row_of_pair[2 * s + 1];
    float w0 = g_rw[2 * s + 0];
    float w1 = g_rw[2 * s + 1];
    const __nv_bfloat162* y0p = (const __nv_bfloat162*)(g_y + (size_t)r0 * D) + j * 2;
    const __nv_bfloat162* y1p = (const __nv_bfloat162*)(g_y + (size_t)r1 * D) + j * 2;
    float2 a0 = __bfloat1622float2(y0p[0]);
    float2 a1 = __bfloat1622float2(y0p[1]);
    float2 b0 = __bfloat1622float2(y1p[0]);
    float2 b1 = __bfloat1622float2(y1p[1]);
    float4 o;
    o.x = w0 * a0.x + w1 * b0.x;
    o.y = w0 * a0.y + w1 * b0.y;
    o.z = w0 * a1.x + w1 * b1.x;
    o.w = w0 * a1.y + w1 * b1.y;
    ((float4*)(out + (size_t)s * D))[j] = o;
}

// ---------------- launch ----------------
extern "C" void kernel_launch(void* const* d_in, const int* in_sizes, int n_in,
                              void* d_out, int out_size) {
    const float* x  = (const float*)d_in[0];   // hidden_states [S, D]
    const float* gw = (const float*)d_in[1];   // gate_w [E, D]
    const float* Wg = (const float*)d_in[2];   // w_gate [E, H, D]
    const float* Wu = (const float*)d_in[3];   // w_up   [E, H, D]
    const float* Wd = (const float*)d_in[4];   // w_down [E, D, H]
    float* out = (float*)d_out;

    size_t base = (size_t)S * D;
    float* logits_out = nullptr;
    float* topi_out = nullptr;
    if ((size_t)out_size >= base + (size_t)S * E) logits_out = out + base;
    if ((size_t)out_size >= base + (size_t)S * E + (size_t)S * TOPK)
        topi_out = out + base + (size_t)S * E;

    __nv_bfloat16* wg_dst; cudaGetSymbolAddress((void**)&wg_dst, g_wg);
    __nv_bfloat16* wu_dst; cudaGetSymbolAddress((void**)&wu_dst, g_wu);
    __nv_bfloat16* wd_dst; cudaGetSymbolAddress((void**)&wd_dst, g_wd);
    __nv_bfloat16* xb_dst; cudaGetSymbolAddress((void**)&xb_dst, g_xb);

    int n4 = (E * H * D) / 4;
    int xn4 = (S * D) / 4;
    int cvt_grid = (3 * n4 + xn4 + 255) / 256;

    cvt_all_kernel<<<cvt_grid, 256>>>((const float4*)Wg, (const float4*)Wu, (const float4*)Wd,
                                      (const float4*)x,
                                      (__nv_bfloat162*)wg_dst, (__nv_bfloat162*)wu_dst,
                                      (__nv_bfloat162*)wd_dst, (__nv_bfloat162*)xb_dst,
                                      n4, xn4);                               // 1 (zeroes g_cnt)
    router_kernel<<<(S * 32) / 256, 256>>>(x, gw, logits_out, topi_out);      // 2
    scan_scatter_kernel<<<1, 1024>>>();                                       // 3
    gemm1_kernel<<<dim3(H / BN, P / BM, E), 256>>>();                         // 4  <- profiled
    gemm2_kernel<<<dim3(D / BN, P / BM, E), 256>>>();                         // 5
    combine_kernel<<<(S * (D / 4) + 255) / 256, 256>>>(out);                  // 6
}

// round 17
// speedup vs baseline: 1.1877x; 1.1877x over previous
#include <cuda_runtime.h>
#include <cuda_bf16.h>
#include <cstdint>

// Problem constants
static constexpr int S = 4096;
static constexpr int D = 1024;
static constexpr int H = 2816;
static constexpr int E = 16;
static constexpr int TOPK = 2;
static constexpr int P = S * TOPK;   // 8192 dispatched rows

// GEMM tiling: BK=64, 2-stage ring, dynamic smem
static constexpr int BM = 128;
static constexpr int BN = 64;
static constexpr int BK = 64;
static constexpr int LDA = 72;   // 64 + 8 pad (144B rows; ldsm conflict-free)
static constexpr int LDB = 72;
static constexpr int A_STAGE = BM * LDA * 2;   // 18432 B
static constexpr int B_STAGE = BN * LDB * 2;   // 9216 B
static constexpr int SM1_TOTAL = 2 * A_STAGE + 4 * B_STAGE;  // 73728 B
static constexpr int SM2_TOTAL = 2 * A_STAGE + 2 * B_STAGE;  // 55296 B

// -------- device scratch (allocation-free: static device globals) --------
__device__ __nv_bfloat16 g_xs[(size_t)P * D];       // gathered tokens, bf16     (16 MB)
__device__ __nv_bfloat16 g_h[(size_t)P * H];        // silu(g)*u, bf16           (45 MB)
__device__ __nv_bfloat16 g_y[(size_t)P * D];        // down-proj result, bf16    (16 MB)
__device__ __nv_bfloat16 g_wg[(size_t)E * H * D];   // w_gate bf16               (92 MB)
__device__ __nv_bfloat16 g_wu[(size_t)E * H * D];   // w_up bf16                 (92 MB)
__device__ __nv_bfloat16 g_wd[(size_t)E * D * H];   // w_down bf16               (92 MB)
__device__ float         g_rw[P];                   // normalized router weights
__device__ int           g_expert[P];               // expert id per (token,k)
__device__ int           g_row_of_pair[P];          // pair -> sorted row
__device__ int           g_perm[P];                 // sorted row -> pair
__device__ int           g_cnt[E];
__device__ int           g_off[E];

// ---------------- small helpers ----------------
__device__ __forceinline__ void ldsm_x4(uint32_t& r0, uint32_t& r1, uint32_t& r2, uint32_t& r3,
                                        const __nv_bfloat16* p) {
    uint32_t addr = (uint32_t)__cvta_generic_to_shared(p);
    asm volatile("ldmatrix.sync.aligned.m8n8.x4.shared.b16 {%0,%1,%2,%3}, [%4];\n"
                 : "=r"(r0), "=r"(r1), "=r"(r2), "=r"(r3) : "r"(addr));
}

__device__ __forceinline__ void mma16816(float* c, const uint32_t* a, const uint32_t* b) {
    asm volatile("mma.sync.aligned.m16n8k16.row.col.f32.bf16.bf16.f32 "
                 "{%0,%1,%2,%3}, {%4,%5,%6,%7}, {%8,%9}, {%0,%1,%2,%3};\n"
                 : "+f"(c[0]), "+f"(c[1]), "+f"(c[2]), "+f"(c[3])
                 : "r"(a[0]), "r"(a[1]), "r"(a[2]), "r"(a[3]), "r"(b[0]), "r"(b[1]));
}

__device__ __forceinline__ void cp_async16(__nv_bfloat16* smem_dst, const __nv_bfloat16* gsrc,
                                           bool valid) {
    uint32_t d = (uint32_t)__cvta_generic_to_shared(smem_dst);
    int sz = valid ? 16 : 0;
    asm volatile("cp.async.cg.shared.global [%0], [%1], 16, %2;\n" :: "r"(d), "l"(gsrc), "r"(sz));
}
__device__ __forceinline__ void cp_commit() { asm volatile("cp.async.commit_group;\n" ::: "memory"); }
template <int N>
__device__ __forceinline__ void cp_wait() { asm volatile("cp.async.wait_group %0;\n" :: "n"(N) : "memory"); }

// bf16 round-trip: emulate the reference's ragged_dot bf16 output then fp32 cast
__device__ __forceinline__ float bf16_round(float v) {
    return __bfloat162float(__float2bfloat16_rn(v));
}
// fast silu: __expf error (~1e-6 rel) is absorbed by the subsequent bf16 rounding
__device__ __forceinline__ float fast_silu_mul(float g, float u) {
    return __fdividef(g, 1.f + __expf(-g)) * u;
}

// ---------------- kernel 1: weight conversion fp32->bf16 + counter init ----------------
__global__ void cvt_all_kernel(const float4* __restrict__ Wg, const float4* __restrict__ Wu,
                               const float4* __restrict__ Wd,
                               __nv_bfloat162* __restrict__ og, __nv_bfloat162* __restrict__ ou,
                               __nv_bfloat162* __restrict__ od, int n4) {
    int i = blockIdx.x * blockDim.x + threadIdx.x;
    if (blockIdx.x == 0 && threadIdx.x < E) g_cnt[threadIdx.x] = 0;
    if (i >= 3 * n4) return;
    const float4* src;
    __nv_bfloat162* dst;
    int j = i;
    if (j < n4)            { src = Wg; dst = og; }
    else if (j < 2 * n4)   { src = Wu; dst = ou; j -= n4; }
    else                   { src = Wd; dst = od; j -= 2 * n4; }
    float4 v = src[j];
    dst[j * 2 + 0] = __floats2bfloat162_rn(v.x, v.y);
    dst[j * 2 + 1] = __floats2bfloat162_rn(v.z, v.w);
}

// ---------------- kernel 2: router (one warp per token) ----------------
__global__ void router_kernel(const float* __restrict__ x, const float* __restrict__ gw,
                              float* __restrict__ logits_out, float* __restrict__ topi_out) {
    int gwarp = (blockIdx.x * blockDim.x + threadIdx.x) >> 5;
    int lane = threadIdx.x & 31;
    if (gwarp >= S) return;

    const float4* xr = (const float4*)(x + (size_t)gwarp * D);
    float acc[E];
#pragma unroll
    for (int e = 0; e < E; e++) acc[e] = 0.f;
    for (int j = lane; j < D / 4; j += 32) {
        float4 xv = xr[j];
#pragma unroll
        for (int e = 0; e < E; e++) {
            float4 wv = ((const float4*)(gw + (size_t)e * D))[j];
            acc[e] += xv.x * wv.x + xv.y * wv.y + xv.z * wv.z + xv.w * wv.w;
        }
    }
#pragma unroll
    for (int e = 0; e < E; e++) {
#pragma unroll
        for (int o = 16; o > 0; o >>= 1) acc[e] += __shfl_xor_sync(0xffffffffu, acc[e], o);
    }
    if (logits_out && lane < E) logits_out[(size_t)gwarp * E + lane] = acc[lane];

    if (lane == 0) {
        float m = acc[0];
#pragma unroll
        for (int e = 1; e < E; e++) m = fmaxf(m, acc[e]);
        float p[E];
        float sum = 0.f;
#pragma unroll
        for (int e = 0; e < E; e++) { p[e] = expf(acc[e] - m); sum += p[e]; }
        // top-2 with lowest-index tie break (matches jax.lax.top_k)
        int i0 = 0;
#pragma unroll
        for (int e = 1; e < E; e++) if (p[e] > p[i0]) i0 = e;
        int i1 = (i0 == 0) ? 1 : 0;
#pragma unroll
        for (int e = 0; e < E; e++) { if (e == i0) continue; if (p[e] > p[i1]) i1 = e; }
        float w0 = p[i0] / sum, w1 = p[i1] / sum;
        float inv = 1.f / (w0 + w1);
        g_expert[gwarp * 2 + 0] = i0;
        g_expert[gwarp * 2 + 1] = i1;
        g_rw[gwarp * 2 + 0] = w0 * inv;
        g_rw[gwarp * 2 + 1] = w1 * inv;
        atomicAdd(&g_cnt[i0], 1);
        atomicAdd(&g_cnt[i1], 1);
        if (topi_out) {
            topi_out[gwarp * 2 + 0] = (float)i0;
            topi_out[gwarp * 2 + 1] = (float)i1;
        }
    }
}

// ---------------- kernel 3: fused scan + scatter (single block) ----------------
__global__ void scan_scatter_kernel() {
    __shared__ int scur[E];
    int t = threadIdx.x;
    if (t == 0) {
        int o = 0;
        for (int e = 0; e < E; e++) { g_off[e] = o; scur[e] = o; o += g_cnt[e]; }
    }
    __syncthreads();
    for (int p = t; p < P; p += blockDim.x) {
        int e = g_expert[p];
        int pos = atomicAdd(&scur[e], 1);
        g_row_of_pair[p] = pos;
        g_perm[pos] = p;
    }
}

// ---------------- kernel 4: gather x rows as bf16 ----------------
__global__ void gather_kernel(const float* __restrict__ x) {
    int row = blockIdx.x;
    int p = g_perm[row];
    int tok = p >> 1;
    const float4* src = (const float4*)(x + (size_t)tok * D);
    __nv_bfloat162* dst = (__nv_bfloat162*)(g_xs + (size_t)row * D);
    int t = threadIdx.x;  // 128 threads, 8 floats each
    float4 v0 = src[t * 2 + 0];
    float4 v1 = src[t * 2 + 1];
    dst[t * 4 + 0] = __floats2bfloat162_rn(v0.x, v0.y);
    dst[t * 4 + 1] = __floats2bfloat162_rn(v0.z, v0.w);
    dst[t * 4 + 2] = __floats2bfloat162_rn(v1.x, v1.y);
    dst[t * 4 + 3] = __floats2bfloat162_rn(v1.z, v1.w);
}

// ---------------- kernel 5: fused gate/up grouped GEMM + SwiGLU ----------------
// grid: (H/BN, 64, E), 256 threads (8 warps, 4x2). BK=64, 2-stage ring, one barrier
// per K-step: cp_wait<0> -> barrier -> prefetch(ks+1) -> compute(ks, 4 kk-halves).
__global__ __launch_bounds__(256, 2) void gemm1_kernel() {
    extern __shared__ __nv_bfloat16 smx[];
    int e = blockIdx.z;
    int cnt = g_cnt[e];
    int mt = blockIdx.y;
    if (mt * BM >= cnt) return;
    int nt = blockIdx.x;
    int row0 = g_off[e] + mt * BM;
    int row_end = g_off[e] + cnt;

    // dynamic smem layout (bf16 elems): As[2][BM*LDA], Bgs[2][BN*LDB], Bus[2][BN*LDB]
    __nv_bfloat16* As0  = smx;
    __nv_bfloat16* Bgs0 = smx + 2 * BM * LDA;
    __nv_bfloat16* Bus0 = smx + 2 * BM * LDA + 2 * BN * LDB;

    int tid = threadIdx.x, lane = tid & 31, warp = tid >> 5;
    int wm = warp >> 1, wn = warp & 1;

    float accg[2][4][4];
    float accu[2][4][4];
#pragma unroll
    for (int a = 0; a < 2; a++)
#pragma unroll
        for (int b = 0; b < 4; b++)
#pragma unroll
            for (int c = 0; c < 4; c++) { accg[a][b][c] = 0.f; accu[a][b][c] = 0.f; }

    const __nv_bfloat16* wg_base = g_wg + ((size_t)e * H + (size_t)nt * BN) * D;
    const __nv_bfloat16* wu_base = g_wu + ((size_t)e * H + (size_t)nt * BN) * D;

    // A tile: 128 rows x 8 segs (16B) = 1024 chunks -> 4/thread
    // B tiles: 64 rows x 8 segs = 512 chunks -> 2/thread each
    auto load_stage = [&](int st, int k0) {
        __nv_bfloat16* Adst = As0 + st * BM * LDA;
        __nv_bfloat16* Gdst = Bgs0 + st * BN * LDB;
        __nv_bfloat16* Udst = Bus0 + st * BN * LDB;
#pragma unroll
        for (int i = 0; i < 4; i++) {
            int c = tid + i * 256;
            int r = c >> 3, seg = c & 7;
            cp_async16(Adst + r * LDA + seg * 8,
                       g_xs + (size_t)(row0 + r) * D + k0 + seg * 8, row0 + r < row_end);
        }
#pragma unroll
        for (int i = 0; i < 2; i++) {
            int c = tid + i * 256;
            int r = c >> 3, seg = c & 7;
            cp_async16(Gdst + r * LDB + seg * 8, wg_base + (size_t)r * D + k0 + seg * 8, true);
            cp_async16(Udst + r * LDB + seg * 8, wu_base + (size_t)r * D + k0 + seg * 8, true);
        }
    };

    constexpr int NK = D / BK;  // 16
    load_stage(0, 0);
    cp_commit();

    for (int ks = 0; ks < NK; ks++) {
        int cur = ks & 1;
        cp_wait<0>();
        __syncthreads();
        if (ks + 1 < NK) {
            load_stage(cur ^ 1, (ks + 1) * BK);
            cp_commit();
        }
        const __nv_bfloat16* Ac = As0 + cur * BM * LDA;
        const __nv_bfloat16* Gc = Bgs0 + cur * BN * LDB;
        const __nv_bfloat16* Uc = Bus0 + cur * BN * LDB;

#pragma unroll
        for (int kk = 0; kk < BK; kk += 16) {
            uint32_t af[2][4];
#pragma unroll
            for (int mf = 0; mf < 2; mf++) {
                int mbase = wm * 32 + mf * 16;
                int row = mbase + (lane & 7) + ((lane >> 3) & 1) * 8;
                int col = kk + (lane >> 4) * 8;
                ldsm_x4(af[mf][0], af[mf][1], af[mf][2], af[mf][3], Ac + row * LDA + col);
            }
            uint32_t bg[4][2], bu[4][2];
#pragma unroll
            for (int nfp = 0; nfp < 2; nfp++) {
                int tile = lane >> 3;
                int n = wn * 32 + nfp * 16 + (tile >> 1) * 8 + (lane & 7);
                int c = kk + (tile & 1) * 8;
                ldsm_x4(bg[nfp * 2][0], bg[nfp * 2][1], bg[nfp * 2 + 1][0], bg[nfp * 2 + 1][1],
                        Gc + n * LDB + c);
                ldsm_x4(bu[nfp * 2][0], bu[nfp * 2][1], bu[nfp * 2 + 1][0], bu[nfp * 2 + 1][1],
                        Uc + n * LDB + c);
            }
#pragma unroll
            for (int mf = 0; mf < 2; mf++)
#pragma unroll
                for (int nf = 0; nf < 4; nf++) {
                    mma16816(&accg[mf][nf][0], af[mf], bg[nf]);
                    mma16816(&accu[mf][nf][0], af[mf], bu[nf]);
                }
        }
    }

    // Epilogue: reference rounds g and u to bf16 (ragged_dot output dtype),
    // casts to fp32, applies silu in fp32, multiplies, then casts to bf16.
    int gr = lane >> 2, gc = (lane & 3) * 2;
#pragma unroll
    for (int mf = 0; mf < 2; mf++) {
#pragma unroll
        for (int nf = 0; nf < 4; nf++) {
            int col = nt * BN + wn * 32 + nf * 8 + gc;
            int r0g = row0 + wm * 32 + mf * 16 + gr;
            int r1g = r0g + 8;
            if (r0g < row_end) {
                float gg0 = bf16_round(accg[mf][nf][0]);
                float gg1 = bf16_round(accg[mf][nf][1]);
                float uu0 = bf16_round(accu[mf][nf][0]);
                float uu1 = bf16_round(accu[mf][nf][1]);
                float s0 = fast_silu_mul(gg0, uu0);
                float s1 = fast_silu_mul(gg1, uu1);
                *(__nv_bfloat162*)(g_h + (size_t)r0g * H + col) = __floats2bfloat162_rn(s0, s1);
            }
            if (r1g < row_end) {
                float gg2 = bf16_round(accg[mf][nf][2]);
                float gg3 = bf16_round(accg[mf][nf][3]);
                float uu2 = bf16_round(accu[mf][nf][2]);
                float uu3 = bf16_round(accu[mf][nf][3]);
                float s2 = fast_silu_mul(gg2, uu2);
                float s3 = fast_silu_mul(gg3, uu3);
                *(__nv_bfloat162*)(g_h + (size_t)r1g * H + col) = __floats2bfloat162_rn(s2, s3);
            }
        }
    }
}

// ---------------- kernel 6: down-proj grouped GEMM ----------------
// grid: (D/BN, 64, E), 256 threads. BK=64, 2-stage ring, one barrier per K-step.
__global__ __launch_bounds__(256, 2) void gemm2_kernel() {
    extern __shared__ __nv_bfloat16 smx[];
    int e = blockIdx.z;
    int cnt = g_cnt[e];
    int mt = blockIdx.y;
    if (mt * BM >= cnt) return;
    int nt = blockIdx.x;
    int row0 = g_off[e] + mt * BM;
    int row_end = g_off[e] + cnt;

    __nv_bfloat16* As0 = smx;
    __nv_bfloat16* Bs0 = smx + 2 * BM * LDA;

    int tid = threadIdx.x, lane = tid & 31, warp = tid >> 5;
    int wm = warp >> 1, wn = warp & 1;

    float acc[2][4][4];
#pragma unroll
    for (int a = 0; a < 2; a++)
#pragma unroll
        for (int b = 0; b < 4; b++)
#pragma unroll
            for (int c = 0; c < 4; c++) acc[a][b][c] = 0.f;

    const __nv_bfloat16* wd_base = g_wd + ((size_t)e * D + (size_t)nt * BN) * H;

    auto load_stage = [&](int st, int k0) {
        __nv_bfloat16* Adst = As0 + st * BM * LDA;
        __nv_bfloat16* Bdst = Bs0 + st * BN * LDB;
#pragma unroll
        for (int i = 0; i < 4; i++) {
            int c = tid + i * 256;
            int r = c >> 3, seg = c & 7;
            cp_async16(Adst + r * LDA + seg * 8,
                       g_h + (size_t)(row0 + r) * H + k0 + seg * 8, row0 + r < row_end);
        }
#pragma unroll
        for (int i = 0; i < 2; i++) {
            int c = tid + i * 256;
            int r = c >> 3, seg = c & 7;
            cp_async16(Bdst + r * LDB + seg * 8, wd_base + (size_t)r * H + k0 + seg * 8, true);
        }
    };

    constexpr int NK = H / BK;  // 44
    load_stage(0, 0);
    cp_commit();

    for (int ks = 0; ks < NK; ks++) {
        int cur = ks & 1;
        cp_wait<0>();
        __syncthreads();
        if (ks + 1 < NK) {
            load_stage(cur ^ 1, (ks + 1) * BK);
            cp_commit();
        }
        const __nv_bfloat16* Ac = As0 + cur * BM * LDA;
        const __nv_bfloat16* Bc = Bs0 + cur * BN * LDB;

#pragma unroll
        for (int kk = 0; kk < BK; kk += 16) {
            uint32_t af[2][4];
#pragma unroll
            for (int mf = 0; mf < 2; mf++) {
                int mbase = wm * 32 + mf * 16;
                int row = mbase + (lane & 7) + ((lane >> 3) & 1) * 8;
                int col = kk + (lane >> 4) * 8;
                ldsm_x4(af[mf][0], af[mf][1], af[mf][2], af[mf][3], Ac + row * LDA + col);
            }
            uint32_t bf[4][2];
#pragma unroll
            for (int nfp = 0; nfp < 2; nfp++) {
                int tile = lane >> 3;
                int n = wn * 32 + nfp * 16 + (tile >> 1) * 8 + (lane & 7);
                int c = kk + (tile & 1) * 8;
                ldsm_x4(bf[nfp * 2][0], bf[nfp * 2][1], bf[nfp * 2 + 1][0], bf[nfp * 2 + 1][1],
                        Bc + n * LDB + c);
            }
#pragma unroll
            for (int mf = 0; mf < 2; mf++)
#pragma unroll
                for (int nf = 0; nf < 4; nf++) mma16816(&acc[mf][nf][0], af[mf], bf[nf]);
        }
    }

    int gr = lane >> 2, gc = (lane & 3) * 2;
#pragma unroll
    for (int mf = 0; mf < 2; mf++) {
#pragma unroll
        for (int nf = 0; nf < 4; nf++) {
            int col = nt * BN + wn * 32 + nf * 8 + gc;
            int r0g = row0 + wm * 32 + mf * 16 + gr;
            int r1g = r0g + 8;
            if (r0g < row_end)
                *(__nv_bfloat162*)(g_y + (size_t)r0g * D + col) =
                    __floats2bfloat162_rn(acc[mf][nf][0], acc[mf][nf][1]);
            if (r1g < row_end)
                *(__nv_bfloat162*)(g_y + (size_t)r1g * D + col) =
                    __floats2bfloat162_rn(acc[mf][nf][2], acc[mf][nf][3]);
        }
    }
}

// ---------------- kernel 7: weighted combine (fp32 math over bf16 y) ----------------
__global__ void combine_kernel(float* __restrict__ out) {
    int idx = blockIdx.x * blockDim.x + threadIdx.x;
    if (idx >= S * (D / 4)) return;
    int s = idx / (D / 4);
    int j = idx % (D / 4);
    int r0 = g_row_of_pair[2 * s + 0];
    int r1 = g_row_of_pair[2 * s + 1];
    float w0 = g_rw[2 * s + 0];
    float w1 = g_rw[2 * s + 1];
    const __nv_bfloat162* y0p = (const __nv_bfloat162*)(g_y + (size_t)r0 * D) + j * 2;
    const __nv_bfloat162* y1p = (const __nv_bfloat162*)(g_y + (size_t)r1 * D) + j * 2;
    float2 a0 = __bfloat1622float2(y0p[0]);
    float2 a1 = __bfloat1622float2(y0p[1]);
    float2 b0 = __bfloat1622float2(y1p[0]);
    float2 b1 = __bfloat1622float2(y1p[1]);
    float4 o;
    o.x = w0 * a0.x + w1 * b0.x;
    o.y = w0 * a0.y + w1 * b0.y;
    o.z = w0 * a1.x + w1 * b1.x;
    o.w = w0 * a1.y + w1 * b1.y;
    ((float4*)(out + (size_t)s * D))[j] = o;
}

// ---------------- launch ----------------
extern "C" void kernel_launch(void* const* d_in, const int* in_sizes, int n_in,
                              void* d_out, int out_size) {
    const float* x  = (const float*)d_in[0];   // hidden_states [S, D]
    const float* gw = (const float*)d_in[1];   // gate_w [E, D]
    const float* Wg = (const float*)d_in[2];   // w_gate [E, H, D]
    const float* Wu = (const float*)d_in[3];   // w_up   [E, H, D]
    const float* Wd = (const float*)d_in[4];   // w_down [E, D, H]
    float* out = (float*)d_out;

    size_t base = (size_t)S * D;
    float* logits_out = nullptr;
    float* topi_out = nullptr;
    if ((size_t)out_size >= base + (size_t)S * E) logits_out = out + base;
    if ((size_t)out_size >= base + (size_t)S * E + (size_t)S * TOPK)
        topi_out = out + base + (size_t)S * E;

    __nv_bfloat16* wg_dst; cudaGetSymbolAddress((void**)&wg_dst, g_wg);
    __nv_bfloat16* wu_dst; cudaGetSymbolAddress((void**)&wu_dst, g_wu);
    __nv_bfloat16* wd_dst; cudaGetSymbolAddress((void**)&wd_dst, g_wd);

    // opt-in to >48KB dynamic smem (idempotent; host-side, capture-safe)
    cudaFuncSetAttribute(gemm1_kernel, cudaFuncAttributeMaxDynamicSharedMemorySize, SM1_TOTAL);
    cudaFuncSetAttribute(gemm2_kernel, cudaFuncAttributeMaxDynamicSharedMemorySize, SM2_TOTAL);

    int n4 = (E * H * D) / 4;
    int cvt_grid = (3 * n4 + 255) / 256;

    cvt_all_kernel<<<cvt_grid, 256>>>((const float4*)Wg, (const float4*)Wu, (const float4*)Wd,
                                      (__nv_bfloat162*)wg_dst, (__nv_bfloat162*)wu_dst,
                                      (__nv_bfloat162*)wd_dst, n4);          // zeroes g_cnt
    router_kernel<<<(S * 32) / 256, 256>>>(x, gw, logits_out, topi_out);
    scan_scatter_kernel<<<1, 1024>>>();
    gather_kernel<<<P, 128>>>(x);
    gemm1_kernel<<<dim3(H / BN, P / BM, E), 256, SM1_TOTAL>>>();
    gemm2_kernel<<<dim3(D / BN, P / BM, E), 256, SM2_TOTAL>>>();
    combine_kernel<<<(S * (D / 4) + 255) / 256, 256>>>(out);
}